// round 3
// baseline (speedup 1.0000x reference)
#include <cuda_runtime.h>
#include <cuda_bf16.h>
#include <math.h>

#define N_NODES 50000
#define N_EDGES 800000
#define N_FEAT  128
#define N_GRAPHS 100

// ---------------- device scratch (no allocation allowed; 16B aligned) ----------------
__device__ __align__(16) int   d_cnt[N_NODES];
__device__ __align__(16) float d_dinv[N_NODES];
__device__ __align__(16) int   d_off[N_NODES + 2];
__device__ __align__(16) int   d_cursor[N_NODES];
__device__ __align__(16) int   d_src[N_EDGES];
__device__ __align__(16) float d_t[(size_t)N_NODES * 128];
__device__ __align__(16) float d_h[(size_t)N_NODES * 128];

// ---------------- CSR build ----------------
__global__ void zero_cnt_kernel(int* __restrict__ cnt) {
    int i = blockIdx.x * blockDim.x + threadIdx.x;
    if (i < N_NODES) cnt[i] = 0;
}

__global__ void count_kernel(const int* __restrict__ col, int* __restrict__ cnt) {
    int e = blockIdx.x * blockDim.x + threadIdx.x;
    if (e < N_EDGES) {
        unsigned c = (unsigned)col[e];
        if (c < N_NODES) atomicAdd(cnt + c, 1);
    }
}

// single-block exclusive scan over cnt -> off, cursor; also dinv = rsqrt(cnt+1)
__global__ void scan_kernel(const int* __restrict__ cnt, int* __restrict__ off,
                            int* __restrict__ cursor, float* __restrict__ dinv) {
    __shared__ int wsum[32];
    __shared__ int s_carry;
    const int n = N_NODES;
    int lane = threadIdx.x & 31, wid = threadIdx.x >> 5;
    if (threadIdx.x == 0) s_carry = 0;
    __syncthreads();
    for (int base = 0; base < n; base += 1024) {
        int i = base + (int)threadIdx.x;
        int v = (i < n) ? cnt[i] : 0;
        int x = v;
        #pragma unroll
        for (int d = 1; d < 32; d <<= 1) {
            int y = __shfl_up_sync(0xffffffffu, x, d);
            if (lane >= d) x += y;
        }
        if (lane == 31) wsum[wid] = x;
        __syncthreads();
        if (wid == 0) {
            int s = wsum[lane];
            #pragma unroll
            for (int d = 1; d < 32; d <<= 1) {
                int y = __shfl_up_sync(0xffffffffu, s, d);
                if (lane >= d) s += y;
            }
            wsum[lane] = s;
        }
        __syncthreads();
        int warp_excl = (wid == 0) ? 0 : wsum[wid - 1];
        int excl = s_carry + warp_excl + x - v;
        if (i < n) {
            off[i] = excl;
            cursor[i] = excl;
            dinv[i] = rsqrtf((float)(v + 1));   // +1 for self loop
        }
        __syncthreads();
        if (threadIdx.x == 0) s_carry += wsum[31];
        __syncthreads();
    }
    if (threadIdx.x == 0) off[n] = s_carry;
}

__global__ void fill_kernel(const int* __restrict__ row,
                            const int* __restrict__ col,
                            int* __restrict__ cursor, int* __restrict__ src) {
    int e = blockIdx.x * blockDim.x + threadIdx.x;
    if (e < N_EDGES) {
        unsigned c = (unsigned)col[e];
        if (c < N_NODES) {
            int pos = atomicAdd(cursor + c, 1);
            if ((unsigned)pos < N_EDGES) src[pos] = row[e];
        }
    }
}

// ---------------- GEMM: t[v] = dinv[v] * (A[v] @ W), A is [M,128], W is [128,NOUT] ----------------
template <int NOUT>
__global__ void gemm_dinv_kernel(const float* __restrict__ A,
                                 const float* __restrict__ W,
                                 const float* __restrict__ dinv,
                                 float* __restrict__ T) {
    constexpr int BM = 64, BK = 16, TM = 8, TN = 4;
    constexpr int NTH = (BM / TM) * (NOUT / TN);
    __shared__ __align__(16) float As[BK][BM];
    __shared__ __align__(16) float Ws[BK][NOUT];
    const int M = N_NODES;
    int tid = threadIdx.x;
    int tx = tid % (NOUT / TN);
    int ty = tid / (NOUT / TN);
    int row0 = blockIdx.x * BM;
    float acc[TM][TN];
    #pragma unroll
    for (int i = 0; i < TM; i++)
        #pragma unroll
        for (int j = 0; j < TN; j++) acc[i][j] = 0.f;

    for (int kt = 0; kt < 128; kt += BK) {
        // load A tile (transposed into smem)
        for (int i = tid; i < BM * BK / 4; i += NTH) {
            int r = i >> 2;       // 4 float4 per row of BK
            int c4 = i & 3;
            int grow = row0 + r;
            float4 q = make_float4(0.f, 0.f, 0.f, 0.f);
            if (grow < M)
                q = *reinterpret_cast<const float4*>(A + (size_t)grow * 128 + kt + c4 * 4);
            As[c4 * 4 + 0][r] = q.x;
            As[c4 * 4 + 1][r] = q.y;
            As[c4 * 4 + 2][r] = q.z;
            As[c4 * 4 + 3][r] = q.w;
        }
        // load W tile
        for (int i = tid; i < BK * NOUT / 4; i += NTH) {
            int kr = i / (NOUT / 4);
            int c4 = i % (NOUT / 4);
            float4 q = *reinterpret_cast<const float4*>(W + (size_t)(kt + kr) * NOUT + c4 * 4);
            Ws[kr][c4 * 4 + 0] = q.x;
            Ws[kr][c4 * 4 + 1] = q.y;
            Ws[kr][c4 * 4 + 2] = q.z;
            Ws[kr][c4 * 4 + 3] = q.w;
        }
        __syncthreads();
        #pragma unroll
        for (int k = 0; k < BK; k++) {
            float a[TM], b[TN];
            #pragma unroll
            for (int i = 0; i < TM; i++) a[i] = As[k][ty * TM + i];
            #pragma unroll
            for (int j = 0; j < TN; j++) b[j] = Ws[k][tx * TN + j];
            #pragma unroll
            for (int i = 0; i < TM; i++)
                #pragma unroll
                for (int j = 0; j < TN; j++) acc[i][j] += a[i] * b[j];
        }
        __syncthreads();
    }
    #pragma unroll
    for (int i = 0; i < TM; i++) {
        int r = row0 + ty * TM + i;
        if (r < M) {
            float dv = dinv[r];
            #pragma unroll
            for (int j = 0; j < TN; j++)
                T[(size_t)r * NOUT + tx * TN + j] = dv * acc[i][j];
        }
    }
}

// ---------------- aggregation: h[v] = relu(dinv[v]*(t[v] + sum_in t[src]) + b) ----------------
template <int F>
__global__ void agg_kernel(const float* __restrict__ T,
                           const int* __restrict__ off,
                           const int* __restrict__ src,
                           const float* __restrict__ dinv,
                           const float* __restrict__ bias,
                           float* __restrict__ H) {
    constexpr int V = F / 32;
    int warp = threadIdx.x >> 5, lane = threadIdx.x & 31;
    int v = blockIdx.x * (blockDim.x >> 5) + warp;
    if (v >= N_NODES) return;
    int f0 = lane * V;
    float acc[V];
    #pragma unroll
    for (int i = 0; i < V; i++) acc[i] = T[(size_t)v * F + f0 + i];
    int e0 = off[v], e1 = off[v + 1];
    for (int e = e0; e < e1; e++) {
        int s = src[e];
        const float* ts = T + (size_t)s * F + f0;
        #pragma unroll
        for (int i = 0; i < V; i++) acc[i] += ts[i];
    }
    float dv = dinv[v];
    float* hv = H + (size_t)v * F + f0;
    #pragma unroll
    for (int i = 0; i < V; i++) {
        float o = dv * acc[i] + bias[f0 + i];
        hv[i] = fmaxf(o, 0.f);
    }
}

// ---------------- pooling + MLP ----------------
__device__ __forceinline__ int lb32(const int* __restrict__ b, int n, int key) {
    int lo = 0, hi = n;
    while (lo < hi) {
        int mid = (lo + hi) >> 1;
        if (b[mid] < key) lo = mid + 1; else hi = mid;
    }
    return lo;
}

__global__ void pool_mlp_kernel(const float* __restrict__ H,
                                const int* __restrict__ batch,
                                const float* __restrict__ Wf1, const float* __restrict__ bf1,
                                const float* __restrict__ Wf2, const float* __restrict__ bf2,
                                float* __restrict__ out) {
    __shared__ float partial[256];
    __shared__ float pooled[64];
    __shared__ float hid[32];
    int g = blockIdx.x;
    int start = lb32(batch, N_NODES, g);
    int end   = lb32(batch, N_NODES, g + 1);
    int cnt = end - start;
    int t = threadIdx.x;
    int feat = t & 63;
    int strip = t >> 6;            // 0..3
    float s = 0.f;
    for (int i = start + strip; i < end; i += 4)
        s += H[(size_t)i * 64 + feat];
    partial[t] = s;
    __syncthreads();
    if (t < 64) {
        float tot = partial[t] + partial[t + 64] + partial[t + 128] + partial[t + 192];
        pooled[t] = tot / fmaxf((float)cnt, 1.0f);
    }
    __syncthreads();
    if (t < 32) {
        float a = bf1[t];
        #pragma unroll 8
        for (int k = 0; k < 64; k++) a += pooled[k] * Wf1[k * 32 + t];
        hid[t] = fmaxf(a, 0.f);
    }
    __syncthreads();
    if (t < 10) {
        float a = bf2[t];
        #pragma unroll
        for (int k = 0; k < 32; k++) a += hid[k] * Wf2[k * 10 + t];
        out[g * 10 + t] = a;
    }
}

// ---------------- launch ----------------
extern "C" void kernel_launch(void* const* d_in, const int* in_sizes, int n_in,
                              void* d_out, int out_size) {
    const float* x     = (const float*)d_in[0];
    const int*   ei    = (const int*)d_in[1];     // int32 (JAX x64 disabled)
    const int*   batch = (const int*)d_in[2];     // int32
    const float* W1 = (const float*)d_in[3];
    const float* b1 = (const float*)d_in[4];
    const float* W2 = (const float*)d_in[5];
    const float* b2 = (const float*)d_in[6];
    const float* W3 = (const float*)d_in[7];
    const float* b3 = (const float*)d_in[8];
    const float* Wf1 = (const float*)d_in[9];
    const float* bf1 = (const float*)d_in[10];
    const float* Wf2 = (const float*)d_in[11];
    const float* bf2 = (const float*)d_in[12];
    float* out = (float*)d_out;

    const int* row = ei;              // edge_index[0]
    const int* col = ei + N_EDGES;    // edge_index[1]

    // resolve scratch symbol addresses (pure lookup, graph-capture safe)
    int *p_cnt = nullptr, *p_off = nullptr, *p_cursor = nullptr, *p_src = nullptr;
    float *p_dinv = nullptr, *p_t = nullptr, *p_h = nullptr;
    cudaGetSymbolAddress((void**)&p_cnt,    d_cnt);
    cudaGetSymbolAddress((void**)&p_off,    d_off);
    cudaGetSymbolAddress((void**)&p_cursor, d_cursor);
    cudaGetSymbolAddress((void**)&p_src,    d_src);
    cudaGetSymbolAddress((void**)&p_dinv,   d_dinv);
    cudaGetSymbolAddress((void**)&p_t,      d_t);
    cudaGetSymbolAddress((void**)&p_h,      d_h);

    // CSR build
    zero_cnt_kernel<<<(N_NODES + 255) / 256, 256>>>(p_cnt);
    count_kernel<<<(N_EDGES + 255) / 256, 256>>>(col, p_cnt);
    scan_kernel<<<1, 1024>>>(p_cnt, p_off, p_cursor, p_dinv);
    fill_kernel<<<(N_EDGES + 255) / 256, 256>>>(row, col, p_cursor, p_src);

    const int GEMM_BLOCKS = (N_NODES + 63) / 64;
    const int AGG_BLOCKS = (N_NODES + 7) / 8;

    // layer 1: 128 -> 128
    gemm_dinv_kernel<128><<<GEMM_BLOCKS, 256>>>(x,   W1, p_dinv, p_t);
    agg_kernel<128><<<AGG_BLOCKS, 256>>>(p_t, p_off, p_src, p_dinv, b1, p_h);
    // layer 2: 128 -> 128
    gemm_dinv_kernel<128><<<GEMM_BLOCKS, 256>>>(p_h, W2, p_dinv, p_t);
    agg_kernel<128><<<AGG_BLOCKS, 256>>>(p_t, p_off, p_src, p_dinv, b2, p_h);
    // layer 3: 128 -> 64
    gemm_dinv_kernel<64><<<GEMM_BLOCKS, 128>>>(p_h, W3, p_dinv, p_t);
    agg_kernel<64><<<AGG_BLOCKS, 256>>>(p_t, p_off, p_src, p_dinv, b3, p_h);

    // pool + MLP
    pool_mlp_kernel<<<N_GRAPHS, 256>>>(p_h, batch, Wf1, bf1, Wf2, bf2, out);
}

// round 5
// speedup vs baseline: 1.0437x; 1.0437x over previous
#include <cuda_runtime.h>
#include <cuda_bf16.h>
#include <math.h>
#include <stdint.h>

#define N_NODES 50000
#define N_EDGES 800000
#define N_GRAPHS 100

// ---------------- device scratch (no allocation allowed; 16B aligned) ----------------
__device__ __align__(16) int   d_cnt[N_NODES];
__device__ __align__(16) float d_dinv[N_NODES];
__device__ __align__(16) int   d_off[N_NODES + 2];
__device__ __align__(16) int   d_cursor[N_NODES];
__device__ __align__(16) int   d_src[N_EDGES];
__device__ __align__(16) int   d_bsum[64];
__device__ __align__(16) float d_t[(size_t)N_NODES * 128];
__device__ __align__(16) float d_h[(size_t)N_NODES * 128];

// ---------------- packed f32x2 helpers ----------------
__device__ __forceinline__ unsigned long long pk2(float x) {
    unsigned long long r;
    asm("mov.b64 %0, {%1, %1};" : "=l"(r) : "r"(__float_as_uint(x)));
    return r;
}
#define FMA2(acc, a, b) \
    asm("fma.rn.f32x2 %0, %1, %2, %0;" : "+l"(acc) : "l"(a), "l"(b))
#define MUL2(d, a, b) \
    asm("mul.rn.f32x2 %0, %1, %2;" : "=l"(d) : "l"(a), "l"(b))

// ---------------- CSR build ----------------
__global__ void zero_cnt_kernel(int* __restrict__ cnt) {
    int i = blockIdx.x * blockDim.x + threadIdx.x;
    if (i < N_NODES) cnt[i] = 0;
}

__global__ void count_kernel(const int* __restrict__ col, int* __restrict__ cnt) {
    int e = blockIdx.x * blockDim.x + threadIdx.x;
    if (e < N_EDGES) {
        unsigned c = (unsigned)col[e];
        if (c < N_NODES) atomicAdd(cnt + c, 1);
    }
}

__global__ void scan1_kernel(const int* __restrict__ cnt, int* __restrict__ off,
                             float* __restrict__ dinv, int* __restrict__ bsum) {
    __shared__ int ws[32];
    int i = blockIdx.x * 1024 + threadIdx.x;
    int lane = threadIdx.x & 31, wid = threadIdx.x >> 5;
    int v = (i < N_NODES) ? cnt[i] : 0;
    int x = v;
    #pragma unroll
    for (int d = 1; d < 32; d <<= 1) {
        int y = __shfl_up_sync(0xffffffffu, x, d);
        if (lane >= d) x += y;
    }
    if (lane == 31) ws[wid] = x;
    __syncthreads();
    if (wid == 0) {
        int s = ws[lane];
        #pragma unroll
        for (int d = 1; d < 32; d <<= 1) {
            int y = __shfl_up_sync(0xffffffffu, s, d);
            if (lane >= d) s += y;
        }
        ws[lane] = s;
    }
    __syncthreads();
    int excl = (wid ? ws[wid - 1] : 0) + x - v;
    if (i < N_NODES) {
        off[i] = excl;
        dinv[i] = rsqrtf((float)(v + 1));
    }
    if (threadIdx.x == 0) bsum[blockIdx.x] = ws[31];
}

// parallel scan of block sums (nb <= 64)
__global__ void scan2_kernel(int* __restrict__ bsum, int* __restrict__ off, int nb) {
    __shared__ int wtot[2];
    int t = threadIdx.x;               // 64 threads
    int lane = t & 31, w = t >> 5;
    int v = (t < nb) ? bsum[t] : 0;
    int x = v;
    #pragma unroll
    for (int d = 1; d < 32; d <<= 1) {
        int y = __shfl_up_sync(0xffffffffu, x, d);
        if (lane >= d) x += y;
    }
    if (lane == 31) wtot[w] = x;
    __syncthreads();
    int add = (w == 1) ? wtot[0] : 0;
    int excl = add + x - v;
    if (t < nb) bsum[t] = excl;
    if (t == nb - 1) off[N_NODES] = excl + v;
}

__global__ void scan3_kernel(int* __restrict__ off, int* __restrict__ cursor,
                             const int* __restrict__ bsum) {
    int i = blockIdx.x * 1024 + threadIdx.x;
    if (i < N_NODES) {
        int o = off[i] + bsum[blockIdx.x];
        off[i] = o;
        cursor[i] = o;
    }
}

__global__ void fill_kernel(const int* __restrict__ row,
                            const int* __restrict__ col,
                            int* __restrict__ cursor, int* __restrict__ src) {
    int e = blockIdx.x * blockDim.x + threadIdx.x;
    if (e < N_EDGES) {
        unsigned c = (unsigned)col[e];
        if (c < N_NODES) {
            int pos = atomicAdd(cursor + c, 1);
            if ((unsigned)pos < N_EDGES) src[pos] = row[e];
        }
    }
}

// ---------------- GEMM: T[v] = dinv[v] * (A[v] @ W), fp32 via packed f32x2 ----------------
// BM=128 rows per CTA, K=128 resident, NOUT in {128, 64}. 256 threads.
// Thread (tx,ty) = (tid&15, tid>>4) computes rows ty*8..+8, cols tx*(2*TNP)..
template <int NOUT>
__global__ void __launch_bounds__(256, 1)
gemm_f2_kernel(const float* __restrict__ A, const float* __restrict__ W,
               const float* __restrict__ dinv, float* __restrict__ T) {
    constexpr int TNP = NOUT / 32;           // f32x2 pairs per thread: 4 or 2
    extern __shared__ __align__(16) float smem[];
    float* As = smem;                        // [128][128], k-major: As[k*128 + r]
    float* Ws = smem + 128 * 128;            // [128][NOUT]
    int tid = threadIdx.x;
    int row0 = blockIdx.x * 128;

    // load A transposed into As[k][r]; lane==row -> conflict-free STS
    #pragma unroll
    for (int n = 0; n < 16; n++) {
        int i = tid + n * 256;
        int r = i & 127;
        int c4 = i >> 7;                     // 0..31
        int gr = row0 + r;
        float4 q = make_float4(0.f, 0.f, 0.f, 0.f);
        if (gr < N_NODES)
            q = *reinterpret_cast<const float4*>(A + (size_t)gr * 128 + c4 * 4);
        As[(c4 * 4 + 0) * 128 + r] = q.x;
        As[(c4 * 4 + 1) * 128 + r] = q.y;
        As[(c4 * 4 + 2) * 128 + r] = q.z;
        As[(c4 * 4 + 3) * 128 + r] = q.w;
    }
    // load W straight (row-major [128][NOUT])
    for (int i = tid; i < 128 * NOUT / 4; i += 256)
        reinterpret_cast<float4*>(Ws)[i] = reinterpret_cast<const float4*>(W)[i];
    __syncthreads();

    int tx = tid & 15, ty = tid >> 4;
    int r0 = ty * 8;
    int c0 = tx * (TNP * 2);

    unsigned long long acc[8][TNP];
    #pragma unroll
    for (int i = 0; i < 8; i++)
        #pragma unroll
        for (int p = 0; p < TNP; p++) acc[i][p] = 0ULL;

    #pragma unroll 4
    for (int k = 0; k < 128; k++) {
        const float* ar = As + k * 128 + r0;
        float4 a03 = *reinterpret_cast<const float4*>(ar);
        float4 a47 = *reinterpret_cast<const float4*>(ar + 4);
        unsigned long long ap[8];
        ap[0] = pk2(a03.x); ap[1] = pk2(a03.y); ap[2] = pk2(a03.z); ap[3] = pk2(a03.w);
        ap[4] = pk2(a47.x); ap[5] = pk2(a47.y); ap[6] = pk2(a47.z); ap[7] = pk2(a47.w);
        unsigned long long bp[TNP];
        const float* wr = Ws + k * NOUT + c0;
        {
            ulonglong2 u0 = *reinterpret_cast<const ulonglong2*>(wr);
            bp[0] = u0.x; bp[1] = u0.y;
            if (TNP == 4) {
                ulonglong2 u1 = *reinterpret_cast<const ulonglong2*>(wr + 4);
                bp[2] = u1.x; bp[3] = u1.y;
            }
        }
        #pragma unroll
        for (int i = 0; i < 8; i++)
            #pragma unroll
            for (int p = 0; p < TNP; p++)
                FMA2(acc[i][p], ap[i], bp[p]);
    }

    // epilogue: scale by dinv, vector store
    #pragma unroll
    for (int i = 0; i < 8; i++) {
        int r = row0 + r0 + i;
        if (r < N_NODES) {
            unsigned long long dvp = pk2(dinv[r]);
            unsigned long long o[TNP];
            #pragma unroll
            for (int p = 0; p < TNP; p++) MUL2(o[p], acc[i][p], dvp);
            float* dst = T + (size_t)r * NOUT + c0;
            ulonglong2 s0; s0.x = o[0]; s0.y = o[1];
            *reinterpret_cast<ulonglong2*>(dst) = s0;
            if (TNP == 4) {
                ulonglong2 s1; s1.x = o[2]; s1.y = o[3];
                *reinterpret_cast<ulonglong2*>(dst + 4) = s1;
            }
        }
    }
}

// ---------------- aggregation: h[v] = relu(dinv[v]*(t[v] + sum_in t[src]) + b) ----------------
template <int F>
__global__ void agg_kernel(const float* __restrict__ T,
                           const int* __restrict__ off,
                           const int* __restrict__ src,
                           const float* __restrict__ dinv,
                           const float* __restrict__ bias,
                           float* __restrict__ H) {
    constexpr int V = F / 32;
    int warp = threadIdx.x >> 5, lane = threadIdx.x & 31;
    int v = blockIdx.x * (blockDim.x >> 5) + warp;
    if (v >= N_NODES) return;
    int f0 = lane * V;
    float acc[V];
    #pragma unroll
    for (int i = 0; i < V; i++) acc[i] = T[(size_t)v * F + f0 + i];
    int e0 = off[v], e1 = off[v + 1];
    #pragma unroll 4
    for (int e = e0; e < e1; e++) {
        int s = src[e];
        const float* ts = T + (size_t)s * F + f0;
        #pragma unroll
        for (int i = 0; i < V; i++) acc[i] += ts[i];
    }
    float dv = dinv[v];
    float* hv = H + (size_t)v * F + f0;
    #pragma unroll
    for (int i = 0; i < V; i++) {
        float o = dv * acc[i] + bias[f0 + i];
        hv[i] = fmaxf(o, 0.f);
    }
}

// ---------------- pooling + MLP ----------------
__device__ __forceinline__ int lb32(const int* __restrict__ b, int n, int key) {
    int lo = 0, hi = n;
    while (lo < hi) {
        int mid = (lo + hi) >> 1;
        if (b[mid] < key) lo = mid + 1; else hi = mid;
    }
    return lo;
}

__global__ void pool_mlp_kernel(const float* __restrict__ H,
                                const int* __restrict__ batch,
                                const float* __restrict__ Wf1, const float* __restrict__ bf1,
                                const float* __restrict__ Wf2, const float* __restrict__ bf2,
                                float* __restrict__ out) {
    __shared__ float partial[256];
    __shared__ float pooled[64];
    __shared__ float hid[32];
    int g = blockIdx.x;
    int start = lb32(batch, N_NODES, g);
    int end   = lb32(batch, N_NODES, g + 1);
    int cnt = end - start;
    int t = threadIdx.x;
    int feat = t & 63;
    int strip = t >> 6;
    float s = 0.f;
    for (int i = start + strip; i < end; i += 4)
        s += H[(size_t)i * 64 + feat];
    partial[t] = s;
    __syncthreads();
    if (t < 64) {
        float tot = partial[t] + partial[t + 64] + partial[t + 128] + partial[t + 192];
        pooled[t] = tot / fmaxf((float)cnt, 1.0f);
    }
    __syncthreads();
    if (t < 32) {
        float a = bf1[t];
        #pragma unroll 8
        for (int k = 0; k < 64; k++) a += pooled[k] * Wf1[k * 32 + t];
        hid[t] = fmaxf(a, 0.f);
    }
    __syncthreads();
    if (t < 10) {
        float a = bf2[t];
        #pragma unroll
        for (int k = 0; k < 32; k++) a += hid[k] * Wf2[k * 10 + t];
        out[g * 10 + t] = a;
    }
}

// ---------------- launch ----------------
extern "C" void kernel_launch(void* const* d_in, const int* in_sizes, int n_in,
                              void* d_out, int out_size) {
    const float* x     = (const float*)d_in[0];
    const int*   ei    = (const int*)d_in[1];     // int32 (JAX x64 disabled)
    const int*   batch = (const int*)d_in[2];
    const float* W1 = (const float*)d_in[3];
    const float* b1 = (const float*)d_in[4];
    const float* W2 = (const float*)d_in[5];
    const float* b2 = (const float*)d_in[6];
    const float* W3 = (const float*)d_in[7];
    const float* b3 = (const float*)d_in[8];
    const float* Wf1 = (const float*)d_in[9];
    const float* bf1 = (const float*)d_in[10];
    const float* Wf2 = (const float*)d_in[11];
    const float* bf2 = (const float*)d_in[12];
    float* out = (float*)d_out;

    const int* row = ei;
    const int* col = ei + N_EDGES;

    int *p_cnt, *p_off, *p_cursor, *p_src, *p_bsum;
    float *p_dinv, *p_t, *p_h;
    cudaGetSymbolAddress((void**)&p_cnt,    d_cnt);
    cudaGetSymbolAddress((void**)&p_off,    d_off);
    cudaGetSymbolAddress((void**)&p_cursor, d_cursor);
    cudaGetSymbolAddress((void**)&p_src,    d_src);
    cudaGetSymbolAddress((void**)&p_bsum,   d_bsum);
    cudaGetSymbolAddress((void**)&p_dinv,   d_dinv);
    cudaGetSymbolAddress((void**)&p_t,      d_t);
    cudaGetSymbolAddress((void**)&p_h,      d_h);

    const int SM128 = (128 * 128 + 128 * 128) * 4;   // 128 KB
    const int SM64  = (128 * 128 + 128 * 64) * 4;    //  96 KB
    cudaFuncSetAttribute(gemm_f2_kernel<128>, cudaFuncAttributeMaxDynamicSharedMemorySize, SM128);
    cudaFuncSetAttribute(gemm_f2_kernel<64>,  cudaFuncAttributeMaxDynamicSharedMemorySize, SM64);

    const int SCAN_BLOCKS = (N_NODES + 1023) / 1024;  // 49

    // CSR build
    zero_cnt_kernel<<<(N_NODES + 255) / 256, 256>>>(p_cnt);
    count_kernel<<<(N_EDGES + 255) / 256, 256>>>(col, p_cnt);
    scan1_kernel<<<SCAN_BLOCKS, 1024>>>(p_cnt, p_off, p_dinv, p_bsum);
    scan2_kernel<<<1, 64>>>(p_bsum, p_off, SCAN_BLOCKS);
    scan3_kernel<<<SCAN_BLOCKS, 1024>>>(p_off, p_cursor, p_bsum);
    fill_kernel<<<(N_EDGES + 255) / 256, 256>>>(row, col, p_cursor, p_src);

    const int GB = (N_NODES + 127) / 128;   // 391
    const int AGG_BLOCKS = (N_NODES + 7) / 8;

    gemm_f2_kernel<128><<<GB, 256, SM128>>>(x,   W1, p_dinv, p_t);
    agg_kernel<128><<<AGG_BLOCKS, 256>>>(p_t, p_off, p_src, p_dinv, b1, p_h);
    gemm_f2_kernel<128><<<GB, 256, SM128>>>(p_h, W2, p_dinv, p_t);
    agg_kernel<128><<<AGG_BLOCKS, 256>>>(p_t, p_off, p_src, p_dinv, b2, p_h);
    gemm_f2_kernel<64><<<GB, 256, SM64>>>(p_h, W3, p_dinv, p_t);
    agg_kernel<64><<<AGG_BLOCKS, 256>>>(p_t, p_off, p_src, p_dinv, b3, p_h);

    pool_mlp_kernel<<<N_GRAPHS, 256>>>(p_h, batch, Wf1, bf1, Wf2, bf2, out);
}

// round 6
// speedup vs baseline: 1.0977x; 1.0518x over previous
#include <cuda_runtime.h>
#include <cuda_bf16.h>
#include <math.h>
#include <stdint.h>

#define N_NODES 50000
#define N_EDGES 800000
#define N_GRAPHS 100

// ---------------- device scratch (no allocation allowed; 16B aligned) ----------------
__device__ __align__(16) int   d_cnt[N_NODES];      // stays 0 between calls (re-zeroed by pool_mlp)
__device__ __align__(16) float d_dinv[N_NODES];
__device__ __align__(16) int   d_off[N_NODES];
__device__ __align__(16) int   d_cursor[N_NODES];
__device__ __align__(16) int   d_src[N_EDGES];
__device__ int d_gcur;                               // stays 0 between calls
__device__ __align__(16) float d_t[(size_t)N_NODES * 128];
__device__ __align__(16) float d_h[(size_t)N_NODES * 128];

// ---------------- packed f32x2 helpers ----------------
__device__ __forceinline__ unsigned long long pk2(float x) {
    unsigned long long r;
    asm("mov.b64 %0, {%1, %1};" : "=l"(r) : "r"(__float_as_uint(x)));
    return r;
}
#define FMA2(acc, a, b) \
    asm("fma.rn.f32x2 %0, %1, %2, %0;" : "+l"(acc) : "l"(a), "l"(b))
#define MUL2(d, a, b) \
    asm("mul.rn.f32x2 %0, %1, %2;" : "=l"(d) : "l"(a), "l"(b))

// ---------------- CSR build (scan-free) ----------------
__global__ void count_kernel(const int* __restrict__ col, int* __restrict__ cnt) {
    int e2 = blockIdx.x * blockDim.x + threadIdx.x;
    int e = e2 * 2;
    if (e + 1 < N_EDGES) {
        int2 c = *reinterpret_cast<const int2*>(col + e);
        if ((unsigned)c.x < N_NODES) atomicAdd(cnt + c.x, 1);
        if ((unsigned)c.y < N_NODES) atomicAdd(cnt + c.y, 1);
    } else if (e < N_EDGES) {
        unsigned c = (unsigned)col[e];
        if (c < N_NODES) atomicAdd(cnt + c, 1);
    }
}

// per-block scan + one atomic bump for the block's base; segments disjoint,
// ordering across blocks irrelevant. Also computes dinv.
__global__ void assign_kernel(const int* __restrict__ cnt, int* __restrict__ off,
                              int* __restrict__ cursor, float* __restrict__ dinv,
                              int* __restrict__ gcur) {
    __shared__ int ws[32];
    __shared__ int s_base;
    int i = blockIdx.x * 1024 + threadIdx.x;
    int lane = threadIdx.x & 31, wid = threadIdx.x >> 5;
    int v = (i < N_NODES) ? cnt[i] : 0;
    int x = v;
    #pragma unroll
    for (int d = 1; d < 32; d <<= 1) {
        int y = __shfl_up_sync(0xffffffffu, x, d);
        if (lane >= d) x += y;
    }
    if (lane == 31) ws[wid] = x;
    __syncthreads();
    if (wid == 0) {
        int s = ws[lane];
        #pragma unroll
        for (int d = 1; d < 32; d <<= 1) {
            int y = __shfl_up_sync(0xffffffffu, s, d);
            if (lane >= d) s += y;
        }
        ws[lane] = s;
        if (lane == 31) s_base = atomicAdd(gcur, s);
    }
    __syncthreads();
    int excl = s_base + (wid ? ws[wid - 1] : 0) + x - v;
    if (i < N_NODES) {
        off[i] = excl;
        cursor[i] = excl;
        dinv[i] = rsqrtf((float)(v + 1));
    }
}

__global__ void fill_kernel(const int* __restrict__ row,
                            const int* __restrict__ col,
                            int* __restrict__ cursor, int* __restrict__ src) {
    int e2 = blockIdx.x * blockDim.x + threadIdx.x;
    int e = e2 * 2;
    if (e + 1 < N_EDGES) {
        int2 c = *reinterpret_cast<const int2*>(col + e);
        int2 r = *reinterpret_cast<const int2*>(row + e);
        if ((unsigned)c.x < N_NODES) {
            int pos = atomicAdd(cursor + c.x, 1);
            if ((unsigned)pos < N_EDGES) src[pos] = r.x;
        }
        if ((unsigned)c.y < N_NODES) {
            int pos = atomicAdd(cursor + c.y, 1);
            if ((unsigned)pos < N_EDGES) src[pos] = r.y;
        }
    } else if (e < N_EDGES) {
        unsigned c = (unsigned)col[e];
        if (c < N_NODES) {
            int pos = atomicAdd(cursor + c, 1);
            if ((unsigned)pos < N_EDGES) src[pos] = row[e];
        }
    }
}

// ---------------- GEMM: T[v] = dinv[v] * (A[v] @ W), fp32 via packed f32x2 ----------------
// BM=64 rows per CTA (96/64 KB smem -> 2-3 CTAs/SM), K=128 resident. 128 threads.
template <int NOUT>
__global__ void __launch_bounds__(128, 2)
gemm_f2_kernel(const float* __restrict__ A, const float* __restrict__ W,
               const float* __restrict__ dinv, float* __restrict__ T) {
    constexpr int TNP = NOUT / 32;           // f32x2 pairs per thread: 4 or 2
    constexpr int BM = 64;
    extern __shared__ __align__(16) float smem[];
    float* As = smem;                        // [128][64], k-major: As[k*64 + r]
    float* Ws = smem + 128 * BM;             // [128][NOUT]
    int tid = threadIdx.x;
    int row0 = blockIdx.x * BM;

    // load A transposed into As[k][r]; lanes hit consecutive r -> conflict-free STS
    #pragma unroll
    for (int n = 0; n < 16; n++) {
        int i = tid + n * 128;
        int r = i & 63;
        int c4 = i >> 6;                     // 0..31
        int gr = row0 + r;
        float4 q = make_float4(0.f, 0.f, 0.f, 0.f);
        if (gr < N_NODES)
            q = *reinterpret_cast<const float4*>(A + (size_t)gr * 128 + c4 * 4);
        As[(c4 * 4 + 0) * BM + r] = q.x;
        As[(c4 * 4 + 1) * BM + r] = q.y;
        As[(c4 * 4 + 2) * BM + r] = q.z;
        As[(c4 * 4 + 3) * BM + r] = q.w;
    }
    // load W straight (row-major [128][NOUT])
    for (int i = tid; i < 128 * NOUT / 4; i += 128)
        reinterpret_cast<float4*>(Ws)[i] = reinterpret_cast<const float4*>(W)[i];
    __syncthreads();

    int tx = tid & 15, ty = tid >> 4;        // tx: 16 col-groups, ty: 8 row-groups
    int r0 = ty * 8;
    int c0 = tx * (TNP * 2);

    unsigned long long acc[8][TNP];
    #pragma unroll
    for (int i = 0; i < 8; i++)
        #pragma unroll
        for (int p = 0; p < TNP; p++) acc[i][p] = 0ULL;

    #pragma unroll 8
    for (int k = 0; k < 128; k++) {
        const float* ar = As + k * BM + r0;
        float4 a03 = *reinterpret_cast<const float4*>(ar);
        float4 a47 = *reinterpret_cast<const float4*>(ar + 4);
        unsigned long long ap[8];
        ap[0] = pk2(a03.x); ap[1] = pk2(a03.y); ap[2] = pk2(a03.z); ap[3] = pk2(a03.w);
        ap[4] = pk2(a47.x); ap[5] = pk2(a47.y); ap[6] = pk2(a47.z); ap[7] = pk2(a47.w);
        unsigned long long bp[TNP];
        const float* wr = Ws + k * NOUT + c0;
        {
            ulonglong2 u0 = *reinterpret_cast<const ulonglong2*>(wr);
            bp[0] = u0.x; bp[1] = u0.y;
            if (TNP == 4) {
                ulonglong2 u1 = *reinterpret_cast<const ulonglong2*>(wr + 4);
                bp[2] = u1.x; bp[3] = u1.y;
            }
        }
        #pragma unroll
        for (int i = 0; i < 8; i++)
            #pragma unroll
            for (int p = 0; p < TNP; p++)
                FMA2(acc[i][p], ap[i], bp[p]);
    }

    // epilogue: scale by dinv, vector store
    #pragma unroll
    for (int i = 0; i < 8; i++) {
        int r = row0 + r0 + i;
        if (r < N_NODES) {
            unsigned long long dvp = pk2(dinv[r]);
            unsigned long long o[TNP];
            #pragma unroll
            for (int p = 0; p < TNP; p++) MUL2(o[p], acc[i][p], dvp);
            float* dst = T + (size_t)r * NOUT + c0;
            ulonglong2 s0; s0.x = o[0]; s0.y = o[1];
            *reinterpret_cast<ulonglong2*>(dst) = s0;
            if (TNP == 4) {
                ulonglong2 s1; s1.x = o[2]; s1.y = o[3];
                *reinterpret_cast<ulonglong2*>(dst + 4) = s1;
            }
        }
    }
}

// ---------------- aggregation: h[v] = relu(dinv[v]*(t[v] + sum_in t[src]) + b) ----------------
template <int F>
__global__ void agg_kernel(const float* __restrict__ T,
                           const int* __restrict__ off,
                           const int* __restrict__ cnt,
                           const float* __restrict__ dinv,
                           const float* __restrict__ bias,
                           float* __restrict__ H,
                           const int* __restrict__ src) {
    constexpr int V = F / 32;
    int warp = threadIdx.x >> 5, lane = threadIdx.x & 31;
    int v = blockIdx.x * (blockDim.x >> 5) + warp;
    if (v >= N_NODES) return;
    int f0 = lane * V;
    float acc[V];
    #pragma unroll
    for (int i = 0; i < V; i++) acc[i] = T[(size_t)v * F + f0 + i];
    int e0 = off[v], e1 = e0 + cnt[v];
    #pragma unroll 4
    for (int e = e0; e < e1; e++) {
        int s = src[e];
        const float* ts = T + (size_t)s * F + f0;
        #pragma unroll
        for (int i = 0; i < V; i++) acc[i] += ts[i];
    }
    float dv = dinv[v];
    float* hv = H + (size_t)v * F + f0;
    #pragma unroll
    for (int i = 0; i < V; i++) {
        float o = dv * acc[i] + bias[f0 + i];
        hv[i] = fmaxf(o, 0.f);
    }
}

// ---------------- pooling + MLP (+ cleanup of cnt/gcur for next call) ----------------
__device__ __forceinline__ int lb32(const int* __restrict__ b, int n, int key) {
    int lo = 0, hi = n;
    while (lo < hi) {
        int mid = (lo + hi) >> 1;
        if (b[mid] < key) lo = mid + 1; else hi = mid;
    }
    return lo;
}

__global__ void pool_mlp_kernel(const float* __restrict__ H,
                                const int* __restrict__ batch,
                                const float* __restrict__ Wf1, const float* __restrict__ bf1,
                                const float* __restrict__ Wf2, const float* __restrict__ bf2,
                                float* __restrict__ out,
                                int* __restrict__ cnt, int* __restrict__ gcur) {
    __shared__ float partial[256];
    __shared__ float pooled[64];
    __shared__ float hid[32];
    int g = blockIdx.x;
    int t = threadIdx.x;
    // cleanup: restore invariants for next call
    for (int i = g * 256 + t; i < N_NODES; i += N_GRAPHS * 256) cnt[i] = 0;
    if (g == 0 && t == 0) *gcur = 0;

    int start = lb32(batch, N_NODES, g);
    int end   = lb32(batch, N_NODES, g + 1);
    int n = end - start;
    int feat = t & 63;
    int strip = t >> 6;
    float s = 0.f;
    for (int i = start + strip; i < end; i += 4)
        s += H[(size_t)i * 64 + feat];
    partial[t] = s;
    __syncthreads();
    if (t < 64) {
        float tot = partial[t] + partial[t + 64] + partial[t + 128] + partial[t + 192];
        pooled[t] = tot / fmaxf((float)n, 1.0f);
    }
    __syncthreads();
    if (t < 32) {
        float a = bf1[t];
        #pragma unroll 8
        for (int k = 0; k < 64; k++) a += pooled[k] * Wf1[k * 32 + t];
        hid[t] = fmaxf(a, 0.f);
    }
    __syncthreads();
    if (t < 10) {
        float a = bf2[t];
        #pragma unroll
        for (int k = 0; k < 32; k++) a += hid[k] * Wf2[k * 10 + t];
        out[g * 10 + t] = a;
    }
}

// ---------------- launch ----------------
extern "C" void kernel_launch(void* const* d_in, const int* in_sizes, int n_in,
                              void* d_out, int out_size) {
    const float* x     = (const float*)d_in[0];
    const int*   ei    = (const int*)d_in[1];     // int32 (JAX x64 disabled)
    const int*   batch = (const int*)d_in[2];
    const float* W1 = (const float*)d_in[3];
    const float* b1 = (const float*)d_in[4];
    const float* W2 = (const float*)d_in[5];
    const float* b2 = (const float*)d_in[6];
    const float* W3 = (const float*)d_in[7];
    const float* b3 = (const float*)d_in[8];
    const float* Wf1 = (const float*)d_in[9];
    const float* bf1 = (const float*)d_in[10];
    const float* Wf2 = (const float*)d_in[11];
    const float* bf2 = (const float*)d_in[12];
    float* out = (float*)d_out;

    const int* row = ei;
    const int* col = ei + N_EDGES;

    int *p_cnt, *p_off, *p_cursor, *p_src, *p_gcur;
    float *p_dinv, *p_t, *p_h;
    cudaGetSymbolAddress((void**)&p_cnt,    d_cnt);
    cudaGetSymbolAddress((void**)&p_off,    d_off);
    cudaGetSymbolAddress((void**)&p_cursor, d_cursor);
    cudaGetSymbolAddress((void**)&p_src,    d_src);
    cudaGetSymbolAddress((void**)&p_gcur,   d_gcur);
    cudaGetSymbolAddress((void**)&p_dinv,   d_dinv);
    cudaGetSymbolAddress((void**)&p_t,      d_t);
    cudaGetSymbolAddress((void**)&p_h,      d_h);

    const int SM128 = (128 * 64 + 128 * 128) * 4;   // 96 KB
    const int SM64  = (128 * 64 + 128 * 64) * 4;    // 64 KB
    cudaFuncSetAttribute(gemm_f2_kernel<128>, cudaFuncAttributeMaxDynamicSharedMemorySize, SM128);
    cudaFuncSetAttribute(gemm_f2_kernel<64>,  cudaFuncAttributeMaxDynamicSharedMemorySize, SM64);

    const int E2 = (N_EDGES / 2 + 255) / 256;       // blocks for 2-edge/thread kernels
    const int GB = (N_NODES + 63) / 64;             // 782
    const int AGG_BLOCKS = (N_NODES + 7) / 8;

    // CSR build (3 launches)
    count_kernel<<<E2, 256>>>(col, p_cnt);                                   // 1
    assign_kernel<<<(N_NODES + 1023) / 1024, 1024>>>(p_cnt, p_off, p_cursor, p_dinv, p_gcur); // 2
    fill_kernel<<<E2, 256>>>(row, col, p_cursor, p_src);                     // 3

    gemm_f2_kernel<128><<<GB, 128, SM128>>>(x, W1, p_dinv, p_t);             // 4
    agg_kernel<128><<<AGG_BLOCKS, 256>>>(p_t, p_off, p_cnt, p_dinv, b1, p_h, p_src); // 5
    gemm_f2_kernel<128><<<GB, 128, SM128>>>(p_h, W2, p_dinv, p_t);           // 6 <- ncu -s 5 -c 1
    agg_kernel<128><<<AGG_BLOCKS, 256>>>(p_t, p_off, p_cnt, p_dinv, b2, p_h, p_src); // 7
    gemm_f2_kernel<64><<<GB, 128, SM64>>>(p_h, W3, p_dinv, p_t);             // 8
    agg_kernel<64><<<AGG_BLOCKS, 256>>>(p_t, p_off, p_cnt, p_dinv, b3, p_h, p_src);  // 9

    pool_mlp_kernel<<<N_GRAPHS, 256>>>(p_h, batch, Wf1, bf1, Wf2, bf2, out, p_cnt, p_gcur); // 10
}